// round 1
// baseline (speedup 1.0000x reference)
#include <cuda_runtime.h>

#define NBLK 128
#define TPB  256
#define WID  1024
#define HID  256
#define NST  17
#define NY   273          // 17 + 256
#define XPAD 288
#define RH   8            // WID / NBLK hidden rows per block
#define RL   2            // HID / NBLK output rows per block
#define T_N  64
#define SUB  8
#define NHID 3

// ---------------- global scratch (no allocs allowed) ----------------
__device__ float g_z[2][WID];          // double-buffered layer activations
__device__ float g_k[2][4][NY];        // RK4 slopes, parity-buffered per substep
__device__ unsigned g_count;           // barrier arrival counter (self-resetting)
__device__ volatile unsigned g_gen;    // barrier generation (monotonic)

// ---------------- shared memory layout (floats) ----------------
#define OFF_W0   0
#define OFF_WH   (OFF_W0 + RH*XPAD)        // 2304
#define OFF_WL   (OFF_WH + NHID*RH*WID)    // 26880
#define OFF_Z    (OFF_WL + RL*WID)         // 28928 (16B aligned)
#define OFF_X    (OFF_Z + WID)             // 29952
#define OFF_B0   (OFF_X + XPAD)            // 30240
#define OFF_BH   (OFF_B0 + RH)             // 30248
#define OFF_BL   (OFF_BH + NHID*RH)        // 30272
#define OFF_BB   (OFF_BL + RL)             // 30274
#define OFF_Y    (OFF_BB + 1)              // 30275
#define OFF_BW   (OFF_Y + NY)              // 30548
#define OFF_GEN  (OFF_BW + HID)            // 30804
#define SMEM_FLOATS (OFF_GEN + 4)
#define SMEM_BYTES  (SMEM_FLOATS * 4)

__device__ __forceinline__ void gridbar(unsigned* sgen) {
    __syncthreads();
    if (threadIdx.x == 0) {
        __threadfence();                       // release: prior stcg visible in L2
        unsigned target = *sgen + 1u;
        unsigned old = atomicAdd(&g_count, 1u);
        if (old == NBLK - 1u) {
            g_count = 0u;
            __threadfence();                   // reset visible before release
            g_gen = target;
        } else {
            while (g_gen != target) { }        // volatile spin
        }
        *sgen = target;
    }
    __syncthreads();
}

__device__ __forceinline__ float softplus_f(float v) {
    return fmaxf(v, 0.f) + log1pf(expf(-fabsf(v)));
}

__device__ __forceinline__ float warp_sum(float a) {
#pragma unroll
    for (int o = 16; o > 0; o >>= 1) a += __shfl_xor_sync(0xffffffffu, a, o);
    return a;
}

__global__ void __launch_bounds__(TPB, 1)
ode_kernel(const float* __restrict__ ts,  const float* __restrict__ W0,
           const float* __restrict__ b0,  const float* __restrict__ Wh,
           const float* __restrict__ bh,  const float* __restrict__ Wl,
           const float* __restrict__ bl,  const float* __restrict__ bW,
           const float* __restrict__ bb,  const float* __restrict__ hvec,
           const float* __restrict__ scale, const float* __restrict__ y0log,
           float* __restrict__ out)
{
    extern __shared__ float sm[];
    const int tid  = threadIdx.x;
    const int b    = blockIdx.x;
    const int warp = tid >> 5;
    const int lane = tid & 31;

    float* sW0 = sm + OFF_W0;
    float* sWh = sm + OFF_WH;
    float* sWl = sm + OFF_WL;
    float* sz  = sm + OFF_Z;
    float* sx  = sm + OFF_X;
    float* sb0 = sm + OFF_B0;
    float* sbh = sm + OFF_BH;
    float* sbl = sm + OFF_BL;
    float* sy  = sm + OFF_Y;
    float* sbw = sm + OFF_BW;
    unsigned* sgen = (unsigned*)(sm + OFF_GEN);

    // ---- load weight slices into smem (once per launch) ----
    for (int idx = tid; idx < RH * XPAD; idx += TPB) {
        int r = idx / XPAD, k = idx - r * XPAD;
        sW0[idx] = (k < 273) ? W0[(b * RH + r) * 273 + k] : 0.f;
    }
    for (int idx = tid; idx < NHID * RH * WID; idx += TPB) {
        int l = idx >> 13;            // / (RH*WID)
        int rem = idx & 8191;
        int r = rem >> 10, k = rem & 1023;
        sWh[idx] = Wh[((l * WID) + (b * RH + r)) * WID + k];
    }
    for (int idx = tid; idx < RL * WID; idx += TPB) {
        int r = idx >> 10, k = idx & 1023;
        sWl[idx] = Wl[(b * RL + r) * WID + k];
    }
    if (tid < RH) sb0[tid] = b0[b * RH + tid];
    if (tid >= 32 && tid < 32 + NHID * RH) {
        int i = tid - 32; int l = i / RH, r = i - l * RH;
        sbh[i] = bh[l * WID + b * RH + r];
    }
    if (tid >= 64 && tid < 64 + RL) sbl[tid - 64] = bl[b * RL + (tid - 64)];
    if (tid == 66) sm[OFF_BB] = bb[0];
    for (int idx = tid; idx < HID; idx += TPB) sbw[idx] = bW[idx];
    if (tid >= 96 && tid < 96 + (XPAD - 273)) sx[273 + (tid - 96)] = 0.f;  // pad stays 0

    // ---- init y0 = [softmax(y0_log), hvec] ----
    if (tid == 0) {
        *sgen = g_gen;
        float m = -1e30f;
        for (int i = 0; i < NST; i++) m = fmaxf(m, y0log[i]);
        float s = 0.f, e[NST];
        for (int i = 0; i < NST; i++) { e[i] = expf(y0log[i] - m); s += e[i]; }
        for (int i = 0; i < NST; i++) sy[i] = e[i] / s;
    }
    if (tid < HID) sy[NST + tid] = hvec[tid];
    __syncthreads();

    const float scl = scale[0];

    if (b == 0) {                       // output row 0
        if (tid < NST) out[tid] = sy[tid];
        if (tid < HID) out[T_N * NST + tid] = sy[NST + tid];
    }

    unsigned par = 0;
    for (int iv = 0; iv < T_N - 1; ++iv) {
        float dt = (ts[iv + 1] - ts[iv]) / (float)SUB;
        for (int ss = 0; ss < SUB; ++ss) {
            for (int st = 0; st < 4; ++st) {
                // ---- build MLP input x = [h, state] for this RK stage ----
                float c = (st == 0) ? 0.f : ((st == 3) ? dt : 0.5f * dt);
                for (int j = tid; j < NY; j += TPB) {
                    float yv = sy[j];
                    if (st > 0) yv += c * __ldcg(&g_k[par][st - 1][j]);
                    int xi = (j < NST) ? (HID + j) : (j - NST);
                    sx[xi] = yv;
                }
                __syncthreads();

                // ---- layer 0: 273 -> 1024, one warp per owned row ----
                {
                    float acc = 0.f;
                    const float* w = &sW0[warp * XPAD];
#pragma unroll
                    for (int i = 0; i < 9; i++) {
                        int k = lane + 32 * i;
                        acc = fmaf(w[k], sx[k], acc);
                    }
                    acc = warp_sum(acc);
                    if (lane == 0)
                        __stcg(&g_z[0][b * RH + warp], softplus_f(acc + sb0[warp]));
                }

                // ---- block 0 / warp 0: bb1 + 17-dim dstate (overlaps MLP) ----
                if (b == 0 && warp == 0) {
                    float t = 0.f;
#pragma unroll
                    for (int i = 0; i < 8; i++) {
                        int k = lane + 32 * i;
                        t = fmaf(sbw[k], sx[k], t);
                    }
                    t = warp_sum(t);
                    if (lane == 0) {
                        float bb1 = 8.f / (1.f + expf(-(t + sm[OFF_BB]))) + 25.f;
                        const float MU   = (float)(0.041 / 12.0);
                        const float XI   = (float)(13.0 / 12.0);
                        const float XIMU = (float)(13.0 / 12.0 + 0.041 / 12.0);
                        const float MUSG = (float)(0.041 / 12.0 + 91.0 / 12.0);
                        const float SG   = (float)(91.0 / 12.0);
                        const float NU   = (float)(36.0 / 12.0);
                        const float NUMU = (float)(36.0 / 12.0 + 0.041 / 12.0);
                        const float MUGA = (float)(0.041 / 12.0 + 1.8 / 12.0);
                        const float GA   = (float)(1.8 / 12.0);
                        const float* s_ = &sx[HID];
                        float M  = s_[0],  S1 = s_[1],  E1 = s_[2],  E2 = s_[3];
                        float E3 = s_[4],  E4 = s_[5],  I1 = s_[6],  I2 = s_[7];
                        float I3 = s_[8],  I4 = s_[9],  R1 = s_[10], R2 = s_[11];
                        float R3 = s_[12], R4 = s_[13], S2 = s_[14], S3 = s_[15];
                        float S4 = s_[16];
                        float I = I1 + I2 + I3 + I4;
                        float R = R1 + R2 + R3 + R4;
                        float bb2 = 0.5f * bb1, bb3 = 0.35f * bb1, bb4 = 0.25f * bb1;
                        float d[NST];
                        d[0]  = R * MU - XIMU * M;
                        d[1]  = MU * (1.f - R) + XI * M - MU * S1 - bb1 * I * S1;
                        d[2]  = bb1 * I * S1 - MUSG * E1;
                        d[3]  = bb2 * I * S2 - MUSG * E2;
                        d[4]  = bb3 * I * S3 - MUSG * E3;
                        d[5]  = bb4 * I * S4 - MUSG * E4;
                        d[6]  = SG * E1 - NUMU * I1;
                        d[7]  = SG * E2 - NUMU * I2;
                        d[8]  = SG * E3 - NUMU * I3;
                        d[9]  = SG * E4 - NUMU * I4;
                        d[10] = NU * I1 - MUGA * R1;
                        d[11] = NU * I2 - MUGA * R2;
                        d[12] = NU * I3 - MUGA * R3;
                        d[13] = NU * I4 - MUGA * R4;
                        d[14] = GA * R1 - MU * S2 - bb2 * I * S2;
                        d[15] = GA * R2 - MU * S3 - bb3 * I * S3;
                        d[16] = GA * (R3 + R4) - MU * S4 - bb4 * I * S4;
#pragma unroll
                        for (int i2 = 0; i2 < NST; i2++)
                            __stcg(&g_k[par][st][i2], d[i2]);
                    }
                }

                gridbar(sgen);
                for (int j = tid; j < WID; j += TPB) sz[j] = __ldcg(&g_z[0][j]);
                __syncthreads();

                // ---- 3 hidden layers: 1024 -> 1024 ----
                for (int l = 0; l < NHID; l++) {
                    float acc = 0.f;
                    const float* w = &sWh[(l * RH + warp) * WID];
#pragma unroll
                    for (int i = 0; i < 8; i++) {
                        float4 w4 = *(const float4*)&w[lane * 4 + 128 * i];
                        float4 z4 = *(const float4*)&sz[lane * 4 + 128 * i];
                        acc = fmaf(w4.x, z4.x, acc);
                        acc = fmaf(w4.y, z4.y, acc);
                        acc = fmaf(w4.z, z4.z, acc);
                        acc = fmaf(w4.w, z4.w, acc);
                    }
                    acc = warp_sum(acc);
                    int buf = (l + 1) & 1;
                    if (lane == 0)
                        __stcg(&g_z[buf][b * RH + warp],
                               softplus_f(acc + sbh[l * RH + warp]));
                    gridbar(sgen);
                    for (int j = tid; j < WID; j += TPB) sz[j] = __ldcg(&g_z[buf][j]);
                    __syncthreads();
                }

                // ---- final layer: 1024 -> 256, tanh, dh = scale * u ----
                if (warp < RL) {
                    float acc = 0.f;
                    const float* w = &sWl[warp * WID];
#pragma unroll
                    for (int i = 0; i < 8; i++) {
                        float4 w4 = *(const float4*)&w[lane * 4 + 128 * i];
                        float4 z4 = *(const float4*)&sz[lane * 4 + 128 * i];
                        acc = fmaf(w4.x, z4.x, acc);
                        acc = fmaf(w4.y, z4.y, acc);
                        acc = fmaf(w4.z, z4.z, acc);
                        acc = fmaf(w4.w, z4.w, acc);
                    }
                    acc = warp_sum(acc);
                    if (lane == 0) {
                        float u = tanhf(0.01f * (acc + sbl[warp]));
                        __stcg(&g_k[par][st][NST + b * RL + warp], scl * u);
                    }
                }
                gridbar(sgen);
            } // st

            // ---- RK4 combine (redundant per block, bitwise identical) ----
            float dt6 = dt / 6.0f;
            for (int j = tid; j < NY; j += TPB) {
                float k1 = __ldcg(&g_k[par][0][j]);
                float k2 = __ldcg(&g_k[par][1][j]);
                float k3 = __ldcg(&g_k[par][2][j]);
                float k4 = __ldcg(&g_k[par][3][j]);
                sy[j] += dt6 * (k1 + 2.f * k2 + 2.f * k3 + k4);
            }
            __syncthreads();
            par ^= 1;
        } // ss

        if (b == 0) {
            if (tid < NST) out[(iv + 1) * NST + tid] = sy[tid];
            if (tid < HID) out[T_N * NST + (iv + 1) * HID + tid] = sy[NST + tid];
        }
    } // iv
}

extern "C" void kernel_launch(void* const* d_in, const int* in_sizes, int n_in,
                              void* d_out, int out_size) {
    (void)in_sizes; (void)n_in; (void)out_size;
    const float* ts    = (const float*)d_in[0];
    const float* W0    = (const float*)d_in[1];
    const float* b0    = (const float*)d_in[2];
    const float* Wh    = (const float*)d_in[3];
    const float* bh    = (const float*)d_in[4];
    const float* Wl    = (const float*)d_in[5];
    const float* bl    = (const float*)d_in[6];
    const float* bW    = (const float*)d_in[7];
    const float* bb    = (const float*)d_in[8];
    const float* hvec  = (const float*)d_in[9];
    const float* scale = (const float*)d_in[10];
    const float* y0log = (const float*)d_in[11];
    float* out = (float*)d_out;

    cudaFuncSetAttribute(ode_kernel,
                         cudaFuncAttributeMaxDynamicSharedMemorySize, SMEM_BYTES);
    ode_kernel<<<NBLK, TPB, SMEM_BYTES>>>(ts, W0, b0, Wh, bh, Wl, bl, bW, bb,
                                          hvec, scale, y0log, out);
}

// round 4
// speedup vs baseline: 1.5852x; 1.5852x over previous
#include <cuda_runtime.h>

#define NBLK 128
#define TPB  288          // 9 warps: 8 MLP-row warps + 1 SEIR warp
#define WID  1024
#define HID  256
#define NST  17
#define NY   273          // 17 + 256
#define XPAD 288
#define RH   8            // hidden rows per block
#define RL   2            // output rows per block
#define T_N  64
#define SUB  8
#define NHID 3

// ---------------- global scratch (no allocs allowed) ----------------
__device__ __align__(16) float g_z[2][WID];   // double-buffered layer activations
__device__ float g_k[2][4][NY];               // RK4 slopes, parity-buffered
__device__ unsigned g_cnt;                    // arrival counter (reset each launch)

// ---------------- shared memory layout (floats) ----------------
#define OFF_W0   0
#define OFF_WH   (OFF_W0 + RH*XPAD)        // 2304
#define OFF_WL   (OFF_WH + NHID*RH*WID)    // 26880
#define OFF_Z    (OFF_WL + RL*WID)         // 28928 (16B aligned)
#define OFF_X    (OFF_Z + WID)             // 29952
#define OFF_B0   (OFF_X + XPAD)
#define OFF_BH   (OFF_B0 + RH)
#define OFF_BL   (OFF_BH + NHID*RH)
#define OFF_BB   (OFF_BL + RL)
#define OFF_Y    (OFF_BB + 1)
#define OFF_BW   (OFF_Y + NY)
#define SMEM_FLOATS (OFF_BW + HID)
#define SMEM_BYTES  (SMEM_FLOATS * 4)

__device__ __forceinline__ unsigned ld_acq(unsigned* p) {
    unsigned v;
    asm volatile("ld.acquire.gpu.global.u32 %0, [%1];" : "=r"(v) : "l"(p) : "memory");
    return v;
}
__device__ __forceinline__ void red_rel_add(unsigned* p, unsigned v) {
    asm volatile("red.release.gpu.global.add.u32 [%0], %1;" :: "l"(p), "r"(v) : "memory");
}

// Grid barrier: CTA fence (bar.sync) + release-RED arrival + acquire-load
// poll on a counter that is zeroed by reset_kernel at the start of every
// launch. No MEMBAR, no in-kernel reset, no cross-launch state.
__device__ __forceinline__ void gridbar(unsigned tgt) {
    __syncthreads();
    if (threadIdx.x == 0) {
        red_rel_add(&g_cnt, 1u);
        unsigned v;
        do { v = ld_acq(&g_cnt); } while ((int)(v - tgt) < 0);
    }
    __syncthreads();
}

__device__ __forceinline__ float softplus_f(float v) {
    return fmaxf(v, 0.f) + log1pf(expf(-fabsf(v)));
}

__device__ __forceinline__ float warp_sum(float a) {
#pragma unroll
    for (int o = 16; o > 0; o >>= 1) a += __shfl_xor_sync(0xffffffffu, a, o);
    return a;
}

__global__ void reset_kernel() { g_cnt = 0u; }

__global__ void __launch_bounds__(TPB, 1)
ode_kernel(const float* __restrict__ ts,  const float* __restrict__ W0,
           const float* __restrict__ b0,  const float* __restrict__ Wh,
           const float* __restrict__ bh,  const float* __restrict__ Wl,
           const float* __restrict__ bl,  const float* __restrict__ bW,
           const float* __restrict__ bb,  const float* __restrict__ hvec,
           const float* __restrict__ scale, const float* __restrict__ y0log,
           float* __restrict__ out)
{
    extern __shared__ float sm[];
    const int tid  = threadIdx.x;
    const int b    = blockIdx.x;
    const int warp = tid >> 5;
    const int lane = tid & 31;

    float* sW0 = sm + OFF_W0;
    float* sWh = sm + OFF_WH;
    float* sWl = sm + OFF_WL;
    float* sz  = sm + OFF_Z;
    float* sx  = sm + OFF_X;
    float* sb0 = sm + OFF_B0;
    float* sbh = sm + OFF_BH;
    float* sbl = sm + OFF_BL;
    float* sy  = sm + OFF_Y;
    float* sbw = sm + OFF_BW;

    unsigned tgt = 0;   // barrier target; g_cnt was zeroed by reset_kernel

    // ---- load weight slices into smem (once per launch) ----
    for (int idx = tid; idx < RH * XPAD; idx += TPB) {
        int r = idx / XPAD, k = idx - r * XPAD;
        sW0[idx] = (k < 273) ? W0[(b * RH + r) * 273 + k] : 0.f;
    }
    for (int idx = tid; idx < NHID * RH * WID; idx += TPB) {
        int l = idx >> 13;
        int rem = idx & 8191;
        int r = rem >> 10, k = rem & 1023;
        sWh[idx] = Wh[((l * WID) + (b * RH + r)) * WID + k];
    }
    for (int idx = tid; idx < RL * WID; idx += TPB) {
        int r = idx >> 10, k = idx & 1023;
        sWl[idx] = Wl[(b * RL + r) * WID + k];
    }
    if (tid < RH) sb0[tid] = b0[b * RH + tid];
    if (tid >= 32 && tid < 32 + NHID * RH) {
        int i = tid - 32; int l = i / RH, r = i - l * RH;
        sbh[i] = bh[l * WID + b * RH + r];
    }
    if (tid >= 64 && tid < 64 + RL) sbl[tid - 64] = bl[b * RL + (tid - 64)];
    if (tid == 66) sm[OFF_BB] = bb[0];
    for (int idx = tid; idx < HID; idx += TPB) sbw[idx] = bW[idx];

    // ---- init y0 = [softmax(y0_log), hvec] ----
    if (tid == 0) {
        float m = -1e30f;
        for (int i = 0; i < NST; i++) m = fmaxf(m, y0log[i]);
        float s = 0.f, e[NST];
        for (int i = 0; i < NST; i++) { e[i] = expf(y0log[i] - m); s += e[i]; }
        for (int i = 0; i < NST; i++) sy[i] = e[i] / s;
    }
    if (tid < HID) sy[NST + tid] = hvec[tid];
    __syncthreads();

    const float scl = scale[0];

    if (b == 0) {
        if (tid < NST) out[tid] = sy[tid];
        if (tid < HID) out[T_N * NST + tid] = sy[NST + tid];
    }

    unsigned par = 0;
    for (int iv = 0; iv < T_N - 1; ++iv) {
        float dt = (ts[iv + 1] - ts[iv]) * (1.f / (float)SUB);
        for (int ss = 0; ss < SUB; ++ss) {
            for (int st = 0; st < 4; ++st) {
                float c = (st == 0) ? 0.f : ((st == 3) ? dt : 0.5f * dt);

                // ---- build MLP input x = [h, state] (one pass, 273 thr) ----
                if (tid < NY) {
                    float yv = sy[tid];
                    if (st > 0) yv += c * __ldcg(&g_k[par][st - 1][tid]);
                    sx[(tid < NST) ? (HID + tid) : (tid - NST)] = yv;
                }
                __syncthreads();

                if (warp < 8) {
                    // ---- layer 0: 273 -> 1024, one warp per owned row ----
                    float acc = 0.f;
                    const float* w = &sW0[warp * XPAD];
#pragma unroll
                    for (int i = 0; i < 9; i++) {
                        int k = lane + 32 * i;
                        acc = fmaf(w[k], sx[k], acc);
                    }
                    acc = warp_sum(acc);
                    if (lane == 0)
                        __stcg(&g_z[0][b * RH + warp], softplus_f(acc + sb0[warp]));
                } else if (b == 0) {
                    // ---- dedicated SEIR warp (block 0, warp 8) ----
                    float t = 0.f;
#pragma unroll
                    for (int i = 0; i < 8; i++) {
                        int k = lane + 32 * i;
                        t = fmaf(sbw[k], sx[k], t);
                    }
                    t = warp_sum(t);
                    if (lane == 0) {
                        float bb1 = 8.f / (1.f + expf(-(t + sm[OFF_BB]))) + 25.f;
                        const float MU   = (float)(0.041 / 12.0);
                        const float XI   = (float)(13.0 / 12.0);
                        const float XIMU = (float)(13.0 / 12.0 + 0.041 / 12.0);
                        const float MUSG = (float)(0.041 / 12.0 + 91.0 / 12.0);
                        const float SG   = (float)(91.0 / 12.0);
                        const float NU   = (float)(36.0 / 12.0);
                        const float NUMU = (float)(36.0 / 12.0 + 0.041 / 12.0);
                        const float MUGA = (float)(0.041 / 12.0 + 1.8 / 12.0);
                        const float GA   = (float)(1.8 / 12.0);
                        const float* s_ = &sx[HID];
                        float M  = s_[0],  S1 = s_[1],  E1 = s_[2],  E2 = s_[3];
                        float E3 = s_[4],  E4 = s_[5],  I1 = s_[6],  I2 = s_[7];
                        float I3 = s_[8],  I4 = s_[9],  R1 = s_[10], R2 = s_[11];
                        float R3 = s_[12], R4 = s_[13], S2 = s_[14], S3 = s_[15];
                        float S4 = s_[16];
                        float I = I1 + I2 + I3 + I4;
                        float R = R1 + R2 + R3 + R4;
                        float bb2 = 0.5f * bb1, bb3 = 0.35f * bb1, bb4 = 0.25f * bb1;
                        float d[NST];
                        d[0]  = R * MU - XIMU * M;
                        d[1]  = MU * (1.f - R) + XI * M - MU * S1 - bb1 * I * S1;
                        d[2]  = bb1 * I * S1 - MUSG * E1;
                        d[3]  = bb2 * I * S2 - MUSG * E2;
                        d[4]  = bb3 * I * S3 - MUSG * E3;
                        d[5]  = bb4 * I * S4 - MUSG * E4;
                        d[6]  = SG * E1 - NUMU * I1;
                        d[7]  = SG * E2 - NUMU * I2;
                        d[8]  = SG * E3 - NUMU * I3;
                        d[9]  = SG * E4 - NUMU * I4;
                        d[10] = NU * I1 - MUGA * R1;
                        d[11] = NU * I2 - MUGA * R2;
                        d[12] = NU * I3 - MUGA * R3;
                        d[13] = NU * I4 - MUGA * R4;
                        d[14] = GA * R1 - MU * S2 - bb2 * I * S2;
                        d[15] = GA * R2 - MU * S3 - bb3 * I * S3;
                        d[16] = GA * (R3 + R4) - MU * S4 - bb4 * I * S4;
#pragma unroll
                        for (int i2 = 0; i2 < NST; i2++)
                            __stcg(&g_k[par][st][i2], d[i2]);
                    }
                }
                tgt += NBLK; gridbar(tgt);

                // ---- 3 hidden layers: 1024 -> 1024 ----
#pragma unroll
                for (int l = 0; l < NHID; l++) {
                    int src = l & 1;           // 0,1,0 ; dst = src^1
                    if (tid < 256)
                        *(float4*)&sz[tid * 4] =
                            __ldcg((const float4*)&g_z[src][tid * 4]);
                    __syncthreads();
                    if (warp < 8) {
                        float acc = 0.f;
                        const float4* w4 = (const float4*)&sWh[(l * RH + warp) * WID];
                        const float4* z4 = (const float4*)sz;
#pragma unroll
                        for (int i = 0; i < 8; i++) {
                            float4 a = w4[lane + 32 * i];
                            float4 z = z4[lane + 32 * i];
                            acc = fmaf(a.x, z.x, acc);
                            acc = fmaf(a.y, z.y, acc);
                            acc = fmaf(a.z, z.z, acc);
                            acc = fmaf(a.w, z.w, acc);
                        }
                        acc = warp_sum(acc);
                        if (lane == 0)
                            __stcg(&g_z[src ^ 1][b * RH + warp],
                                   softplus_f(acc + sbh[l * RH + warp]));
                    }
                    tgt += NBLK; gridbar(tgt);
                }

                // ---- final layer: 1024 -> 256, tanh, dh = scale * u ----
                if (tid < 256)
                    *(float4*)&sz[tid * 4] =
                        __ldcg((const float4*)&g_z[1][tid * 4]);
                __syncthreads();
                if (warp < RL) {
                    float acc = 0.f;
                    const float4* w4 = (const float4*)&sWl[warp * WID];
                    const float4* z4 = (const float4*)sz;
#pragma unroll
                    for (int i = 0; i < 8; i++) {
                        float4 a = w4[lane + 32 * i];
                        float4 z = z4[lane + 32 * i];
                        acc = fmaf(a.x, z.x, acc);
                        acc = fmaf(a.y, z.y, acc);
                        acc = fmaf(a.z, z.z, acc);
                        acc = fmaf(a.w, z.w, acc);
                    }
                    acc = warp_sum(acc);
                    if (lane == 0) {
                        float u = tanhf(0.01f * (acc + sbl[warp]));
                        __stcg(&g_k[par][st][NST + b * RL + warp], scl * u);
                    }
                }
                tgt += NBLK; gridbar(tgt);
            } // st

            // ---- RK4 combine (redundant per block, bitwise identical) ----
            float dt6 = dt * (1.f / 6.f);
            if (tid < NY) {
                float k1 = __ldcg(&g_k[par][0][tid]);
                float k2 = __ldcg(&g_k[par][1][tid]);
                float k3 = __ldcg(&g_k[par][2][tid]);
                float k4 = __ldcg(&g_k[par][3][tid]);
                sy[tid] += dt6 * (k1 + 2.f * (k2 + k3) + k4);
            }
            __syncthreads();
            par ^= 1;
        } // ss

        if (b == 0) {
            if (tid < NST) out[(iv + 1) * NST + tid] = sy[tid];
            if (tid < HID) out[T_N * NST + (iv + 1) * HID + tid] = sy[NST + tid];
        }
    } // iv
}

extern "C" void kernel_launch(void* const* d_in, const int* in_sizes, int n_in,
                              void* d_out, int out_size) {
    (void)in_sizes; (void)n_in; (void)out_size;
    const float* ts    = (const float*)d_in[0];
    const float* W0    = (const float*)d_in[1];
    const float* b0    = (const float*)d_in[2];
    const float* Wh    = (const float*)d_in[3];
    const float* bh    = (const float*)d_in[4];
    const float* Wl    = (const float*)d_in[5];
    const float* bl    = (const float*)d_in[6];
    const float* bW    = (const float*)d_in[7];
    const float* bb    = (const float*)d_in[8];
    const float* hvec  = (const float*)d_in[9];
    const float* scale = (const float*)d_in[10];
    const float* y0log = (const float*)d_in[11];
    float* out = (float*)d_out;

    cudaFuncSetAttribute(ode_kernel,
                         cudaFuncAttributeMaxDynamicSharedMemorySize, SMEM_BYTES);
    reset_kernel<<<1, 1>>>();
    ode_kernel<<<NBLK, TPB, SMEM_BYTES>>>(ts, W0, b0, Wh, bh, Wl, bl, bW, bb,
                                          hvec, scale, y0log, out);
}